// round 2
// baseline (speedup 1.0000x reference)
#include <cuda_runtime.h>
#include <math.h>

// Problem constants (fixed by the reference)
#define D     512
#define NHEAD 16
#define HS    32
#define NB    64
#define MAXN  128
#define ATT_SCALE 0.17677669529663687f   // HS^-0.5
#define LN_EPS 1e-5f

#define MAX_ROWS 8192

// Scratch (allocation-free rule: __device__ globals)
__device__ float g_q[MAX_ROWS * D];
__device__ float g_k[MAX_ROWS * D];
__device__ float g_v[MAX_ROWS * D];
__device__ float g_att[MAX_ROWS * D];
__device__ float g_y[MAX_ROWS * D];
__device__ int   g_starts[NB + 1];

// ---------------------------------------------------------------------------
// Kernel 1: segment starts from sorted batch ids
// ---------------------------------------------------------------------------
__global__ void starts_kernel(const int* __restrict__ batch, int N) {
    int i = blockIdx.x * blockDim.x + threadIdx.x;
    if (i >= N) return;
    int b = batch[i];
    if (i == 0 || batch[i - 1] != b) g_starts[b] = i;
    if (i == N - 1) g_starts[NB] = N;
}

// ---------------------------------------------------------------------------
// Kernel 2/4: C[M,512] = A[M,512] @ W[512,512]^T + bias (+ optional residual)
// fp32 tiled SGEMM: BM=128, BN=64, BK=32, 256 threads, 8x4 per-thread tile
// ---------------------------------------------------------------------------
#define BM 128
#define BN 64
#define BK 32

__global__ void __launch_bounds__(256)
gemm_nt(const float* __restrict__ A, const float* __restrict__ W,
        const float* __restrict__ bias, const float* __restrict__ resid,
        float* __restrict__ Cout, int M) {
    __shared__ float As[BK][BM];
    __shared__ float Bs[BK][BN];

    int tid = threadIdx.x;
    int bm = blockIdx.x * BM;
    int bn = blockIdx.y * BN;
    int tx = tid & 15;          // N-dir (16 * 4 = 64)
    int ty = tid >> 4;          // M-dir (16 * 8 = 128)
    int lrow = tid >> 3;        // 0..31  (A stage: 32 rows per pass)
    int lcol = (tid & 7) << 2;  // 0,4,...,28 (8 lanes x float4 = 32 k)

    float acc[8][4];
#pragma unroll
    for (int i = 0; i < 8; i++)
#pragma unroll
        for (int j = 0; j < 4; j++) acc[i][j] = 0.f;

    for (int k0 = 0; k0 < D; k0 += BK) {
        // Stage A tile (128 x 32), transposed into As[k][m]
#pragma unroll
        for (int rr = 0; rr < 4; rr++) {
            int r = lrow + rr * 32;
            float4 v = make_float4(0.f, 0.f, 0.f, 0.f);
            int gr = bm + r;
            if (gr < M)
                v = *reinterpret_cast<const float4*>(&A[(size_t)gr * D + k0 + lcol]);
            As[lcol + 0][r] = v.x;
            As[lcol + 1][r] = v.y;
            As[lcol + 2][r] = v.z;
            As[lcol + 3][r] = v.w;
        }
        // Stage W tile (64 x 32), transposed into Bs[k][n]
#pragma unroll
        for (int rr = 0; rr < 2; rr++) {
            int r = lrow + rr * 32;
            float4 v = *reinterpret_cast<const float4*>(
                &W[(size_t)(bn + r) * D + k0 + lcol]);
            Bs[lcol + 0][r] = v.x;
            Bs[lcol + 1][r] = v.y;
            Bs[lcol + 2][r] = v.z;
            Bs[lcol + 3][r] = v.w;
        }
        __syncthreads();

#pragma unroll
        for (int kk = 0; kk < BK; kk++) {
            float4 a0 = *reinterpret_cast<float4*>(&As[kk][ty * 8]);
            float4 a1 = *reinterpret_cast<float4*>(&As[kk][ty * 8 + 4]);
            float4 bb = *reinterpret_cast<float4*>(&Bs[kk][tx * 4]);
            float a[8] = {a0.x, a0.y, a0.z, a0.w, a1.x, a1.y, a1.z, a1.w};
            float bv[4] = {bb.x, bb.y, bb.z, bb.w};
#pragma unroll
            for (int i = 0; i < 8; i++)
#pragma unroll
                for (int j = 0; j < 4; j++) acc[i][j] += a[i] * bv[j];
        }
        __syncthreads();
    }

#pragma unroll
    for (int i = 0; i < 8; i++) {
        int gr = bm + ty * 8 + i;
        if (gr >= M) continue;
#pragma unroll
        for (int j = 0; j < 4; j++) {
            int gc = bn + tx * 4 + j;
            float v = acc[i][j] + bias[gc];
            if (resid) v += resid[(size_t)gr * D + gc];
            Cout[(size_t)gr * D + gc] = v;
        }
    }
}

// ---------------------------------------------------------------------------
// Kernel 3: attention, one block per (batch, head), one thread per query row.
// K/V tiles in smem, per-thread online (flash) softmax with HS=32 in regs.
// ---------------------------------------------------------------------------
__global__ void __launch_bounds__(128)
attn_kernel(const float* __restrict__ attn_bias) {
    int bh = blockIdx.x;
    int b = bh / NHEAD;
    int h = bh % NHEAD;
    int s0 = g_starts[b];
    int n = g_starts[b + 1] - s0;

    __shared__ float Ks[MAXN][HS];
    __shared__ float Vs[MAXN][HS];

    int tid = threadIdx.x;
    // cooperative K/V stage (float4 per lane)
    for (int i = tid; i < n * (HS / 4); i += blockDim.x) {
        int j = i / (HS / 4);
        int d4 = (i % (HS / 4)) * 4;
        size_t off = (size_t)(s0 + j) * D + h * HS + d4;
        *reinterpret_cast<float4*>(&Ks[j][d4]) =
            *reinterpret_cast<const float4*>(&g_k[off]);
        *reinterpret_cast<float4*>(&Vs[j][d4]) =
            *reinterpret_cast<const float4*>(&g_v[off]);
    }
    __syncthreads();

    int t = tid;
    if (t >= n) return;

    float qr[HS];
#pragma unroll
    for (int d4 = 0; d4 < HS; d4 += 4) {
        float4 v = *reinterpret_cast<const float4*>(
            &g_q[(size_t)(s0 + t) * D + h * HS + d4]);
        qr[d4] = v.x; qr[d4 + 1] = v.y; qr[d4 + 2] = v.z; qr[d4 + 3] = v.w;
    }

    const float* brow =
        attn_bias + (((size_t)b * NHEAD + h) * MAXN + t) * MAXN;

    float m = -INFINITY, l = 0.f;
    float o[HS];
#pragma unroll
    for (int d = 0; d < HS; d++) o[d] = 0.f;

    for (int j = 0; j < n; j++) {
        float dot = 0.f;
#pragma unroll
        for (int d = 0; d < HS; d++) dot += qr[d] * Ks[j][d];
        float s = dot * ATT_SCALE + brow[j];
        float mn = fmaxf(m, s);
        float c = __expf(m - mn);     // first iter: exp(-inf) = 0
        float p = __expf(s - mn);
        l = l * c + p;
#pragma unroll
        for (int d = 0; d < HS; d++) o[d] = o[d] * c + p * Vs[j][d];
        m = mn;
    }

    float inv = 1.f / l;
#pragma unroll
    for (int d = 0; d < HS; d++)
        g_att[(size_t)(s0 + t) * D + h * HS + d] = o[d] * inv;
}

// ---------------------------------------------------------------------------
// Kernel 5: LayerNorm per row (input g_y already = proj + bp + x)
// ---------------------------------------------------------------------------
__global__ void __launch_bounds__(256)
ln_kernel(const float* __restrict__ ln_w, const float* __restrict__ ln_b,
          float* __restrict__ out) {
    int row = blockIdx.x;
    const float* y = g_y + (size_t)row * D;
    int tid = threadIdx.x;

    float v0 = y[tid];
    float v1 = y[tid + 256];
    float s = v0 + v1;
    float q = v0 * v0 + v1 * v1;
#pragma unroll
    for (int off = 16; off; off >>= 1) {
        s += __shfl_down_sync(0xffffffffu, s, off);
        q += __shfl_down_sync(0xffffffffu, q, off);
    }
    __shared__ float rs[8], rq[8];
    __shared__ float s_mu, s_rstd;
    if ((tid & 31) == 0) { rs[tid >> 5] = s; rq[tid >> 5] = q; }
    __syncthreads();
    if (tid == 0) {
        float S = 0.f, Q = 0.f;
#pragma unroll
        for (int i = 0; i < 8; i++) { S += rs[i]; Q += rq[i]; }
        float mu = S * (1.f / D);
        float var = Q * (1.f / D) - mu * mu;
        s_mu = mu;
        s_rstd = rsqrtf(var + LN_EPS);
    }
    __syncthreads();
    float mu = s_mu, r = s_rstd;
    out[(size_t)row * D + tid] = (v0 - mu) * r * ln_w[tid] + ln_b[tid];
    out[(size_t)row * D + tid + 256] =
        (v1 - mu) * r * ln_w[tid + 256] + ln_b[tid + 256];
}

// ---------------------------------------------------------------------------
extern "C" void kernel_launch(void* const* d_in, const int* in_sizes, int n_in,
                              void* d_out, int out_size) {
    const float* x         = (const float*)d_in[0];
    const float* attn_bias = (const float*)d_in[1];
    const float* Wq = (const float*)d_in[2];
    const float* bq = (const float*)d_in[3];
    const float* Wk = (const float*)d_in[4];
    const float* bk = (const float*)d_in[5];
    const float* Wv = (const float*)d_in[6];
    const float* bv = (const float*)d_in[7];
    const float* Wp = (const float*)d_in[8];
    const float* bp = (const float*)d_in[9];
    const float* ln_w = (const float*)d_in[10];
    const float* ln_b = (const float*)d_in[11];
    const int*   batch = (const int*)d_in[12];

    int N = in_sizes[12];            // NTOT (rows)
    float* out = (float*)d_out;

    float *qp, *kp, *vp, *ap, *yp;
    cudaGetSymbolAddress((void**)&qp, g_q);
    cudaGetSymbolAddress((void**)&kp, g_k);
    cudaGetSymbolAddress((void**)&vp, g_v);
    cudaGetSymbolAddress((void**)&ap, g_att);
    cudaGetSymbolAddress((void**)&yp, g_y);

    starts_kernel<<<(N + 255) / 256, 256>>>(batch, N);

    dim3 ggrid((N + BM - 1) / BM, D / BN);
    gemm_nt<<<ggrid, 256>>>(x, Wq, bq, nullptr, qp, N);
    gemm_nt<<<ggrid, 256>>>(x, Wk, bk, nullptr, kp, N);
    gemm_nt<<<ggrid, 256>>>(x, Wv, bv, nullptr, vp, N);

    attn_kernel<<<NB * NHEAD, 128>>>(attn_bias);

    gemm_nt<<<ggrid, 256>>>(ap, Wp, bp, x, yp, N);

    ln_kernel<<<N, 256>>>(ln_w, ln_b, out);
}

// round 5
// speedup vs baseline: 2.2292x; 2.2292x over previous
#include <cuda_runtime.h>
#include <cuda_fp16.h>
#include <math.h>
#include <stdint.h>

// Problem constants
#define D     512
#define NHEAD 16
#define HS    32
#define NB    64
#define MAXN  128
#define ATT_SCALE 0.17677669529663687f
#define LN_EPS 1e-5f
#define MAX_ROWS 8192

// Scratch
__device__ float g_q[MAX_ROWS * D];
__device__ float g_k[MAX_ROWS * D];
__device__ float g_v[MAX_ROWS * D];
__device__ float g_att[MAX_ROWS * D];
__device__ float g_y[MAX_ROWS * D];
__device__ int   g_starts[NB + 1];

#define SWZ128(o) ((o) ^ (((o) >> 3) & 0x70u))

__device__ __forceinline__ uint32_t smem_to_u32(const void* p) {
    uint32_t a;
    asm("{ .reg .u64 t; cvta.to.shared.u64 t, %1; cvt.u32.u64 %0, t; }"
        : "=r"(a) : "l"(p));
    return a;
}
__device__ __forceinline__ void ldsm4(uint32_t* r, uint32_t addr) {
    asm volatile("ldmatrix.sync.aligned.m8n8.x4.shared.b16 {%0,%1,%2,%3}, [%4];"
                 : "=r"(r[0]), "=r"(r[1]), "=r"(r[2]), "=r"(r[3]) : "r"(addr));
}
__device__ __forceinline__ void mma16816(float* c, const uint32_t* a,
                                         const uint32_t* b) {
    asm volatile(
        "mma.sync.aligned.m16n8k16.row.col.f32.f16.f16.f32 "
        "{%0,%1,%2,%3}, {%4,%5,%6,%7}, {%8,%9}, {%0,%1,%2,%3};"
        : "+f"(c[0]), "+f"(c[1]), "+f"(c[2]), "+f"(c[3])
        : "r"(a[0]), "r"(a[1]), "r"(a[2]), "r"(a[3]), "r"(b[0]), "r"(b[1]));
}
__device__ __forceinline__ uint32_t packh(__half a, __half b) {
    __half2 h = __halves2half2(a, b);
    return *reinterpret_cast<uint32_t*>(&h);
}

// ---------------------------------------------------------------------------
// split-fp16 (3-term) mma.sync GEMM: C[M,512] in 128x128 tiles.
// grid.y: 0-3 -> W0 ntiles, 4-7 -> W1, 8-11 -> W2 (fused QKV).
// Smem tile layout: 128 rows x 128B, row = [hi fp16 x32 | lo fp16 x32],
// SW128 XOR swizzle; double-buffered (2 x 32KB).
// ---------------------------------------------------------------------------
#define GBM 128
#define GBK 32
#define NSTAGE (D / GBK)
#define BUFB 32768

__device__ __forceinline__ void cvt_store(char* buf, int row, int cf, float4 v) {
    __half hx = __float2half_rn(v.x), hy = __float2half_rn(v.y);
    __half hz = __float2half_rn(v.z), hw = __float2half_rn(v.w);
    __half lx = __float2half_rn(v.x - __half2float(hx));
    __half ly = __float2half_rn(v.y - __half2float(hy));
    __half lz = __float2half_rn(v.z - __half2float(hz));
    __half lw = __float2half_rn(v.w - __half2float(hw));
    uint2 hi, lo;
    hi.x = packh(hx, hy); hi.y = packh(hz, hw);
    lo.x = packh(lx, ly); lo.y = packh(lz, lw);
    uint32_t off = (uint32_t)(row * 128 + cf * 2);
    *reinterpret_cast<uint2*>(buf + SWZ128(off)) = hi;
    *reinterpret_cast<uint2*>(buf + SWZ128(off + 64)) = lo;
}

__global__ void __launch_bounds__(256, 1)
mma_gemm(const float* __restrict__ A,
         const float* __restrict__ W0, const float* __restrict__ W1,
         const float* __restrict__ W2,
         const float* __restrict__ b0, const float* __restrict__ b1,
         const float* __restrict__ b2,
         float* __restrict__ o0, float* __restrict__ o1, float* __restrict__ o2,
         const float* __restrict__ resid, int M) {
    extern __shared__ __align__(128) char smem[];
    uint32_t sbase = smem_to_u32(smem);
    int tid = threadIdx.x;
    int lane = tid & 31;
    int wid = tid >> 5;
    int warp_m = wid & 1;          // 2 x 64 rows
    int warp_n = wid >> 1;         // 4 x 32 cols
    int bm = blockIdx.x * GBM;
    int ntile = blockIdx.y;
    int wsel = ntile >> 2;
    const float* W    = (wsel == 0) ? W0 : (wsel == 1 ? W1 : W2);
    const float* bias = (wsel == 0) ? b0 : (wsel == 1 ? b1 : b2);
    float* Out        = (wsel == 0) ? o0 : (wsel == 1 ? o1 : o2);
    int nbase = (ntile & 3) * 128;

    // per-thread staging coords: row = lin/8, cf = (lin%8)*4
    int srow = tid >> 3;
    int scf = (tid & 7) << 2;

    float acc[4][4][4];
#pragma unroll
    for (int i = 0; i < 4; i++)
#pragma unroll
        for (int j = 0; j < 4; j++)
#pragma unroll
            for (int k = 0; k < 4; k++) acc[i][j][k] = 0.f;

    // ---- prologue: stage 0
    {
        char* Ab = smem;
        char* Bb = smem + 16384;
#pragma unroll
        for (int i = 0; i < 4; i++) {
            int row = srow + i * 32;
            float4 v = make_float4(0.f, 0.f, 0.f, 0.f);
            int gr = bm + row;
            if (gr < M)
                v = *reinterpret_cast<const float4*>(&A[(size_t)gr * D + scf]);
            cvt_store(Ab, row, scf, v);
            float4 w = *reinterpret_cast<const float4*>(
                &W[(size_t)(nbase + row) * D + scf]);
            cvt_store(Bb, row, scf, w);
        }
    }
    __syncthreads();

    for (int s = 0; s < NSTAGE; s++) {
        // prefetch next stage into registers
        float4 av[4], wv[4];
        if (s + 1 < NSTAGE) {
            int k0 = (s + 1) * GBK;
#pragma unroll
            for (int i = 0; i < 4; i++) {
                int row = srow + i * 32;
                int gr = bm + row;
                av[i] = make_float4(0.f, 0.f, 0.f, 0.f);
                if (gr < M)
                    av[i] = *reinterpret_cast<const float4*>(
                        &A[(size_t)gr * D + k0 + scf]);
                wv[i] = *reinterpret_cast<const float4*>(
                    &W[(size_t)(nbase + row) * D + k0 + scf]);
            }
        }

        // compute from buffer s&1
        uint32_t Abase = sbase + (s & 1) * BUFB;
        uint32_t Bbase = Abase + 16384;
#pragma unroll
        for (int ks = 0; ks < 2; ks++) {
            uint32_t ah[4][4], al[4][4];
#pragma unroll
            for (int mf = 0; mf < 4; mf++) {
                int row = warp_m * 64 + mf * 16 + (lane & 15);
                uint32_t off =
                    (uint32_t)(row * 128 + ks * 32 + ((lane >> 4) << 4));
                ldsm4(ah[mf], Abase + SWZ128(off));
                ldsm4(al[mf], Abase + SWZ128(off + 64));
            }
            uint32_t bh[4][2], bl[4][2];
#pragma unroll
            for (int np = 0; np < 2; np++) {
                int g = lane >> 3;
                int n = warp_n * 32 + np * 16 + ((g >> 1) << 3) + (lane & 7);
                uint32_t off =
                    (uint32_t)(n * 128 + ks * 32 + ((g & 1) << 4));
                uint32_t r[4];
                ldsm4(r, Bbase + SWZ128(off));
                bh[np * 2][0] = r[0]; bh[np * 2][1] = r[1];
                bh[np * 2 + 1][0] = r[2]; bh[np * 2 + 1][1] = r[3];
                ldsm4(r, Bbase + SWZ128(off + 64));
                bl[np * 2][0] = r[0]; bl[np * 2][1] = r[1];
                bl[np * 2 + 1][0] = r[2]; bl[np * 2 + 1][1] = r[3];
            }
#pragma unroll
            for (int mf = 0; mf < 4; mf++)
#pragma unroll
                for (int nf = 0; nf < 4; nf++) {
                    mma16816(acc[mf][nf], ah[mf], bh[nf]);
                    mma16816(acc[mf][nf], ah[mf], bl[nf]);
                    mma16816(acc[mf][nf], al[mf], bh[nf]);
                }
        }

        if (s + 1 < NSTAGE) {
            char* Ab = smem + ((s + 1) & 1) * BUFB;
            char* Bb = Ab + 16384;
#pragma unroll
            for (int i = 0; i < 4; i++) {
                int row = srow + i * 32;
                cvt_store(Ab, row, scf, av[i]);
                cvt_store(Bb, row, scf, wv[i]);
            }
            __syncthreads();
        }
    }

    // ---- epilogue: direct float2 stores with bias (+residual)
#pragma unroll
    for (int mf = 0; mf < 4; mf++) {
#pragma unroll
        for (int nf = 0; nf < 4; nf++) {
            int gc = nbase + warp_n * 32 + nf * 8 + (lane & 3) * 2;
            float2 bb = *reinterpret_cast<const float2*>(&bias[gc]);
            int r0 = bm + warp_m * 64 + mf * 16 + (lane >> 2);
            if (r0 < M) {
                float2 v;
                v.x = acc[mf][nf][0] + bb.x;
                v.y = acc[mf][nf][1] + bb.y;
                if (resid) {
                    float2 rr = *reinterpret_cast<const float2*>(
                        &resid[(size_t)r0 * D + gc]);
                    v.x += rr.x; v.y += rr.y;
                }
                *reinterpret_cast<float2*>(&Out[(size_t)r0 * D + gc]) = v;
            }
            int r1 = r0 + 8;
            if (r1 < M) {
                float2 v;
                v.x = acc[mf][nf][2] + bb.x;
                v.y = acc[mf][nf][3] + bb.y;
                if (resid) {
                    float2 rr = *reinterpret_cast<const float2*>(
                        &resid[(size_t)r1 * D + gc]);
                    v.x += rr.x; v.y += rr.y;
                }
                *reinterpret_cast<float2*>(&Out[(size_t)r1 * D + gc]) = v;
            }
        }
    }
}

// ---------------------------------------------------------------------------
// starts
// ---------------------------------------------------------------------------
__global__ void starts_kernel(const int* __restrict__ batch, int N) {
    int i = blockIdx.x * blockDim.x + threadIdx.x;
    if (i >= N) return;
    int b = batch[i];
    if (i == 0 || batch[i - 1] != b) g_starts[b] = i;
    if (i == N - 1) g_starts[NB] = N;
}

// ---------------------------------------------------------------------------
// attention: one block per (batch, head), one thread per query row.
// KV loop unrolled x4: float4 bias loads, 4 indep dot chains,
// rescale only when group max raises m.
// ---------------------------------------------------------------------------
__global__ void __launch_bounds__(128)
attn_kernel(const float* __restrict__ attn_bias) {
    int bh = blockIdx.x;
    int b = bh / NHEAD;
    int h = bh % NHEAD;
    int s0 = g_starts[b];
    int n = g_starts[b + 1] - s0;

    __shared__ float Ks[MAXN][HS];
    __shared__ float Vs[MAXN][HS];

    int tid = threadIdx.x;
    for (int i = tid; i < n * (HS / 4); i += blockDim.x) {
        int j = i / (HS / 4);
        int d4 = (i % (HS / 4)) * 4;
        size_t off = (size_t)(s0 + j) * D + h * HS + d4;
        *reinterpret_cast<float4*>(&Ks[j][d4]) =
            *reinterpret_cast<const float4*>(&g_k[off]);
        *reinterpret_cast<float4*>(&Vs[j][d4]) =
            *reinterpret_cast<const float4*>(&g_v[off]);
    }
    __syncthreads();

    int t = tid;
    if (t >= n) return;

    float qr[HS];
#pragma unroll
    for (int d4 = 0; d4 < HS; d4 += 4) {
        float4 v = *reinterpret_cast<const float4*>(
            &g_q[(size_t)(s0 + t) * D + h * HS + d4]);
        qr[d4] = v.x; qr[d4 + 1] = v.y; qr[d4 + 2] = v.z; qr[d4 + 3] = v.w;
    }

    const float* brow = attn_bias + (((size_t)b * NHEAD + h) * MAXN + t) * MAXN;

    float m = -INFINITY, l = 0.f;
    float o[HS];
#pragma unroll
    for (int d = 0; d < HS; d++) o[d] = 0.f;

    int j = 0;
    for (; j + 4 <= n; j += 4) {
        float4 b4 = *reinterpret_cast<const float4*>(&brow[j]);
        float sc0 = 0.f, sc1 = 0.f, sc2 = 0.f, sc3 = 0.f;
#pragma unroll
        for (int d = 0; d < HS; d++) {
            float q = qr[d];
            sc0 += q * Ks[j][d];
            sc1 += q * Ks[j + 1][d];
            sc2 += q * Ks[j + 2][d];
            sc3 += q * Ks[j + 3][d];
        }
        sc0 = sc0 * ATT_SCALE + b4.x;
        sc1 = sc1 * ATT_SCALE + b4.y;
        sc2 = sc2 * ATT_SCALE + b4.z;
        sc3 = sc3 * ATT_SCALE + b4.w;
        float gm = fmaxf(fmaxf(sc0, sc1), fmaxf(sc2, sc3));
        if (gm > m) {
            float c = __expf(m - gm);    // first group: exp(-inf)=0
            l *= c;
#pragma unroll
            for (int d = 0; d < HS; d++) o[d] *= c;
            m = gm;
        }
        float p0 = __expf(sc0 - m), p1 = __expf(sc1 - m);
        float p2 = __expf(sc2 - m), p3 = __expf(sc3 - m);
        l += p0 + p1 + p2 + p3;
#pragma unroll
        for (int d = 0; d < HS; d++)
            o[d] += p0 * Vs[j][d] + p1 * Vs[j + 1][d] +
                    p2 * Vs[j + 2][d] + p3 * Vs[j + 3][d];
    }
    for (; j < n; j++) {
        float dot = 0.f;
#pragma unroll
        for (int d = 0; d < HS; d++) dot += qr[d] * Ks[j][d];
        float s = dot * ATT_SCALE + brow[j];
        if (s > m) {
            float c = __expf(m - s);
            l *= c;
#pragma unroll
            for (int d = 0; d < HS; d++) o[d] *= c;
            m = s;
        }
        float p = __expf(s - m);
        l += p;
#pragma unroll
        for (int d = 0; d < HS; d++) o[d] += p * Vs[j][d];
    }

    float inv = 1.f / l;
#pragma unroll
    for (int d = 0; d < HS; d++)
        g_att[(size_t)(s0 + t) * D + h * HS + d] = o[d] * inv;
}

// ---------------------------------------------------------------------------
// LayerNorm
// ---------------------------------------------------------------------------
__global__ void __launch_bounds__(256)
ln_kernel(const float* __restrict__ ln_w, const float* __restrict__ ln_b,
          float* __restrict__ out) {
    int row = blockIdx.x;
    const float* y = g_y + (size_t)row * D;
    int tid = threadIdx.x;

    float v0 = y[tid];
    float v1 = y[tid + 256];
    float s = v0 + v1;
    float q = v0 * v0 + v1 * v1;
#pragma unroll
    for (int off = 16; off; off >>= 1) {
        s += __shfl_down_sync(0xffffffffu, s, off);
        q += __shfl_down_sync(0xffffffffu, q, off);
    }
    __shared__ float rs[8], rq[8];
    __shared__ float s_mu, s_rstd;
    if ((tid & 31) == 0) { rs[tid >> 5] = s; rq[tid >> 5] = q; }
    __syncthreads();
    if (tid == 0) {
        float S = 0.f, Q = 0.f;
#pragma unroll
        for (int i = 0; i < 8; i++) { S += rs[i]; Q += rq[i]; }
        float mu = S * (1.f / D);
        float var = Q * (1.f / D) - mu * mu;
        s_mu = mu;
        s_rstd = rsqrtf(var + LN_EPS);
    }
    __syncthreads();
    float mu = s_mu, r = s_rstd;
    out[(size_t)row * D + tid] = (v0 - mu) * r * ln_w[tid] + ln_b[tid];
    out[(size_t)row * D + tid + 256] =
        (v1 - mu) * r * ln_w[tid + 256] + ln_b[tid + 256];
}

// ---------------------------------------------------------------------------
extern "C" void kernel_launch(void* const* d_in, const int* in_sizes, int n_in,
                              void* d_out, int out_size) {
    const float* x         = (const float*)d_in[0];
    const float* attn_bias = (const float*)d_in[1];
    const float* Wq = (const float*)d_in[2];
    const float* bq = (const float*)d_in[3];
    const float* Wk = (const float*)d_in[4];
    const float* bk = (const float*)d_in[5];
    const float* Wv = (const float*)d_in[6];
    const float* bv = (const float*)d_in[7];
    const float* Wp = (const float*)d_in[8];
    const float* bp = (const float*)d_in[9];
    const float* ln_w = (const float*)d_in[10];
    const float* ln_b = (const float*)d_in[11];
    const int*   batch = (const int*)d_in[12];

    int N = in_sizes[12];
    float* out = (float*)d_out;

    float *qp, *kp, *vp, *ap, *yp;
    cudaGetSymbolAddress((void**)&qp, g_q);
    cudaGetSymbolAddress((void**)&kp, g_k);
    cudaGetSymbolAddress((void**)&vp, g_v);
    cudaGetSymbolAddress((void**)&ap, g_att);
    cudaGetSymbolAddress((void**)&yp, g_y);

    cudaFuncSetAttribute(mma_gemm, cudaFuncAttributeMaxDynamicSharedMemorySize,
                         2 * BUFB);

    starts_kernel<<<(N + 255) / 256, 256>>>(batch, N);

    int mtiles = (N + GBM - 1) / GBM;
    // Fused QKV: grid.y 0-3 -> Wq, 4-7 -> Wk, 8-11 -> Wv
    mma_gemm<<<dim3(mtiles, 12), 256, 2 * BUFB>>>(
        x, Wq, Wk, Wv, bq, bk, bv, qp, kp, vp, nullptr, N);

    attn_kernel<<<NB * NHEAD, 128>>>(attn_bias);

    // Output projection + bias + residual
    mma_gemm<<<dim3(mtiles, 4), 256, 2 * BUFB>>>(
        ap, Wp, Wp, Wp, bp, bp, bp, yp, yp, yp, x, N);

    ln_kernel<<<N, 256>>>(ln_w, ln_b, out);
}